// round 2
// baseline (speedup 1.0000x reference)
#include <cuda_runtime.h>
#include <cuda_bf16.h>
#include <cstdint>

// Problem constants
#define JB 8
#define JT 256
#define JU 64
#define JD 512
#define JV 1024
#define JM (JB * JT * JU)          // 131072 rows
#define MAIN_OUT ((long long)JM * JV)  // 134217728

// ---------------------------------------------------------------------------
// Fused joiner GEMM: out[m, n] = sum_k relu(src[b,t,k] + tgt[b,u,k]) * W[n,k] + bias[n]
// m = (b*T + t)*U + u.  Tile: 128(M) x 128(N) x 16(K).  256 threads, 8x8/thread.
// ---------------------------------------------------------------------------
__global__ __launch_bounds__(256, 2)
void joiner_gemm_kernel(const float* __restrict__ src,   // [B,T,D]
                        const float* __restrict__ tgt,   // [B,U,D]
                        const float* __restrict__ W,     // [V,D]
                        const float* __restrict__ bias,  // [V]
                        float* __restrict__ out)         // [M,V]
{
    __shared__ float sA[16][128];
    __shared__ float sB[16][128];

    const int tid = threadIdx.x;
    const int m0 = blockIdx.y * 128;
    const int n0 = blockIdx.x * 128;

    // Decompose the M-tile: within a 128-row tile (aligned to 128, U=64),
    // b is constant and t spans exactly two consecutive values.
    const int bidx = m0 / (JT * JU);
    const int tu0  = m0 % (JT * JU);
    const int t0   = tu0 / JU;   // tu0 is a multiple of 128, so multiple of 64

    const float* srcB = src + (size_t)bidx * JT * JD;
    const float* tgtB = tgt + (size_t)bidx * JU * JD;

    const int ty = tid >> 4;   // 0..15
    const int tx = tid & 15;   // 0..15

    float acc[8][8];
#pragma unroll
    for (int i = 0; i < 8; i++)
#pragma unroll
        for (int j = 0; j < 8; j++) acc[i][j] = 0.0f;

    for (int k0 = 0; k0 < JD; k0 += 16) {
        // ---- load tiles: 2 float4 per thread for A, 2 for B ----
#pragma unroll
        for (int it = 0; it < 2; it++) {
            const int idx = tid + it * 256;        // 0..511
            const int r   = idx >> 2;              // 0..127
            const int k4  = idx & 3;               // float4 group within 16-k

            // A: relu(src + tgt), rows r -> (t, u)
            const int t = t0 + (r >> 6);
            const int u = r & 63;
            const float4 s4 = *(const float4*)(srcB + (size_t)t * JD + k0 + k4 * 4);
            const float4 g4 = *(const float4*)(tgtB + (size_t)u * JD + k0 + k4 * 4);
            sA[k4 * 4 + 0][r] = fmaxf(s4.x + g4.x, 0.0f);
            sA[k4 * 4 + 1][r] = fmaxf(s4.y + g4.y, 0.0f);
            sA[k4 * 4 + 2][r] = fmaxf(s4.z + g4.z, 0.0f);
            sA[k4 * 4 + 3][r] = fmaxf(s4.w + g4.w, 0.0f);

            // B: W[n0+r, k0 + 4*k4 ..] -> sB[k][n]
            const float4 w4 = *(const float4*)(W + (size_t)(n0 + r) * JD + k0 + k4 * 4);
            sB[k4 * 4 + 0][r] = w4.x;
            sB[k4 * 4 + 1][r] = w4.y;
            sB[k4 * 4 + 2][r] = w4.z;
            sB[k4 * 4 + 3][r] = w4.w;
        }
        __syncthreads();

        // ---- compute 16 k-steps ----
#pragma unroll
        for (int k = 0; k < 16; k++) {
            const float4 a0 = *(const float4*)&sA[k][ty * 4];
            const float4 a1 = *(const float4*)&sA[k][64 + ty * 4];
            const float4 b0 = *(const float4*)&sB[k][tx * 4];
            const float4 b1 = *(const float4*)&sB[k][64 + tx * 4];
            const float av[8] = {a0.x, a0.y, a0.z, a0.w, a1.x, a1.y, a1.z, a1.w};
            const float bv[8] = {b0.x, b0.y, b0.z, b0.w, b1.x, b1.y, b1.z, b1.w};
#pragma unroll
            for (int i = 0; i < 8; i++)
#pragma unroll
                for (int j = 0; j < 8; j++)
                    acc[i][j] = fmaf(av[i], bv[j], acc[i][j]);
        }
        __syncthreads();
    }

    // ---- epilogue: + bias, float4 stores ----
    const float4 bv0 = *(const float4*)(bias + n0 + tx * 4);
    const float4 bv1 = *(const float4*)(bias + n0 + 64 + tx * 4);

#pragma unroll
    for (int i = 0; i < 8; i++) {
        const int r = (i < 4) ? (ty * 4 + i) : (64 + ty * 4 + (i - 4));
        float* orow = out + (size_t)(m0 + r) * JV + n0;
        float4 o0, o1;
        o0.x = acc[i][0] + bv0.x; o0.y = acc[i][1] + bv0.y;
        o0.z = acc[i][2] + bv0.z; o0.w = acc[i][3] + bv0.w;
        o1.x = acc[i][4] + bv1.x; o1.y = acc[i][5] + bv1.y;
        o1.z = acc[i][6] + bv1.z; o1.w = acc[i][7] + bv1.w;
        *(float4*)(orow + tx * 4)      = o0;
        *(float4*)(orow + 64 + tx * 4) = o1;
    }
}

// Tail: append source_lengths / target_lengths (numeric cast) if the flat
// output buffer is larger than the main tensor.
__global__ void joiner_tail_kernel(const int* __restrict__ sl,
                                   const int* __restrict__ tl,
                                   float* __restrict__ out,
                                   long long base, int extra)
{
    const int i = threadIdx.x;
    if (i < 8 && i < extra)           out[base + i]      = (float)sl[i];
    else if (i >= 8 && i < 16 && i < extra) out[base + i] = (float)tl[i - 8];
}

extern "C" void kernel_launch(void* const* d_in, const int* in_sizes, int n_in,
                              void* d_out, int out_size)
{
    // metadata order: source_encodings, source_lengths, target_encodings,
    //                 target_lengths, W, b
    const float* src  = (const float*)d_in[0];
    const int*   sl   = (const int*)  d_in[1];
    const float* tgt  = (const float*)d_in[2];
    const int*   tl   = (const int*)  d_in[3];
    const float* W    = (const float*)d_in[4];
    const float* bias = (const float*)d_in[5];
    float* out = (float*)d_out;

    dim3 grid(JV / 128, JM / 128);   // (8, 1024)
    joiner_gemm_kernel<<<grid, 256>>>(src, tgt, W, bias, out);

    const long long extra = (long long)out_size - MAIN_OUT;
    if (extra > 0) {
        joiner_tail_kernel<<<1, 32>>>(sl, tl, out, MAIN_OUT, (int)extra);
    }
}

// round 6
// speedup vs baseline: 2.1353x; 2.1353x over previous
#include <cuda_runtime.h>
#include <cuda_bf16.h>
#include <cstdint>

// ---------------- problem constants ----------------
#define JB 8
#define JT 256
#define JU 64
#define JD 512
#define JV 1024
#define JM (JB * JT * JU)                 // 131072
#define MAIN_OUT ((long long)JM * JV)     // 134217728

// ---------------- tile config ----------------
#define BM 128
#define BN 128
#define BK 32
#define NCH (JD / BK)          // 16 k-chunks

// smem: padded rows, 32 bf16 (64B) data + 16B pad = 80B stride
#define ROWB 80
#define MATB (128 * ROWB)      // 10240 bytes per matrix tile
// per stage: AH, AL, BH, BL
#define S_AH(s) ((s) * 4 * MATB)
#define S_AL(s) (S_AH(s) + MATB)
#define S_BH(s) (S_AH(s) + 2 * MATB)
#define S_BL(s) (S_AH(s) + 3 * MATB)
#define SMEM_TOT (8 * MATB)    // 81920

// W split into bf16 hi/lo (device scratch; no allocation)
__device__ __nv_bfloat16 g_Wh[JV * JD];
__device__ __nv_bfloat16 g_Wl[JV * JD];

// ---------------- helpers ----------------
__device__ __forceinline__ uint32_t smem_u32(const void* p) {
    uint32_t a;
    asm("{ .reg .u64 t; cvta.to.shared.u64 t, %1; cvt.u32.u64 %0, t; }" : "=r"(a) : "l"(p));
    return a;
}

__device__ __forceinline__ void ldsm_x4(uint32_t* r, uint32_t addr) {
    asm volatile("ldmatrix.sync.aligned.m8n8.x4.shared.b16 {%0,%1,%2,%3}, [%4];"
                 : "=r"(r[0]), "=r"(r[1]), "=r"(r[2]), "=r"(r[3]) : "r"(addr));
}
__device__ __forceinline__ void ldsm_x2(uint32_t* r, uint32_t addr) {
    asm volatile("ldmatrix.sync.aligned.m8n8.x2.shared.b16 {%0,%1}, [%2];"
                 : "=r"(r[0]), "=r"(r[1]) : "r"(addr));
}

__device__ __forceinline__ void mma16816(float* d, const uint32_t* a, const uint32_t* b) {
    asm volatile(
        "mma.sync.aligned.m16n8k16.row.col.f32.bf16.bf16.f32 "
        "{%0,%1,%2,%3}, {%4,%5,%6,%7}, {%8,%9}, {%0,%1,%2,%3};"
        : "+f"(d[0]), "+f"(d[1]), "+f"(d[2]), "+f"(d[3])
        : "r"(a[0]), "r"(a[1]), "r"(a[2]), "r"(a[3]), "r"(b[0]), "r"(b[1]));
}

__device__ __forceinline__ void cp16(uint32_t dst, const void* src) {
    asm volatile("cp.async.cg.shared.global [%0], [%1], 16;" :: "r"(dst), "l"(src) : "memory");
}
#define CP_COMMIT() asm volatile("cp.async.commit_group;" ::: "memory")
#define CP_WAIT0()  asm volatile("cp.async.wait_group 0;" ::: "memory")

// split fp32 pair -> packed bf16x2 hi and lo
__device__ __forceinline__ void split2(float x, float y, uint32_t& hi, uint32_t& lo) {
    __nv_bfloat16 hx = __float2bfloat16_rn(x);
    __nv_bfloat16 hy = __float2bfloat16_rn(y);
    float rx = x - __bfloat162float(hx);
    float ry = y - __bfloat162float(hy);
    __nv_bfloat162 h2; h2.x = hx; h2.y = hy;
    __nv_bfloat162 l2; l2.x = __float2bfloat16_rn(rx); l2.y = __float2bfloat16_rn(ry);
    hi = *reinterpret_cast<uint32_t*>(&h2);
    lo = *reinterpret_cast<uint32_t*>(&l2);
}

// ---------------- W split pre-kernel (+ tail lengths passthrough) ----------------
__global__ void wsplit_kernel(const float* __restrict__ W,
                              const int* __restrict__ sl,
                              const int* __restrict__ tl,
                              float* __restrict__ out,
                              int extra)
{
    int i = blockIdx.x * blockDim.x + threadIdx.x;
    if (i < JV * JD) {
        float w = W[i];
        __nv_bfloat16 h = __float2bfloat16_rn(w);
        g_Wh[i] = h;
        g_Wl[i] = __float2bfloat16_rn(w - __bfloat162float(h));
    }
    if (blockIdx.x == 0) {
        int t = threadIdx.x;
        if (t < 8 && t < extra)                 out[MAIN_OUT + t] = (float)sl[t];
        else if (t >= 8 && t < 16 && t < extra) out[MAIN_OUT + t] = (float)tl[t - 8];
    }
}

// ---------------- main HMMA GEMM ----------------
__global__ __launch_bounds__(256, 1)
void joiner_mma_kernel(const float* __restrict__ src,   // [B,T,D]
                       const float* __restrict__ tgt,   // [B,U,D]
                       const float* __restrict__ bias,  // [V]
                       float* __restrict__ out)         // [M,V]
{
    extern __shared__ char smem[];
    const uint32_t sb = smem_u32(smem);
    const int tid = threadIdx.x;
    const int wid = tid >> 5;
    const int lid = tid & 31;
    const int mw = wid >> 2;       // 0..1 (M)
    const int nw = wid & 3;        // 0..3 (N)

    const int n0 = blockIdx.x * BN;
    const int m0 = blockIdx.y * BM;
    const int bidx = m0 / (JT * JU);
    const int t0 = (m0 % (JT * JU)) / JU;     // tile spans t0, t0+1
    const float* srcB = src + (size_t)bidx * JT * JD;
    const float* tgtB = tgt + (size_t)bidx * JU * JD;

    // ---- per-thread producer geometry (2 items, each 8 cols of one row) ----
    // item i: idx = tid + i*256; r = idx>>2 (0..127); g = idx&3 (k-subgroup of 8)
    int   pr[2], pg[2];
    const float* pSrc[2];
    const float* pTgt[2];
    const __nv_bfloat16* pWh[2];
    const __nv_bfloat16* pWl[2];
    uint32_t stsOff[2];
#pragma unroll
    for (int i = 0; i < 2; i++) {
        const int idx = tid + i * 256;
        pr[i] = idx >> 2;
        pg[i] = idx & 3;
        const int t = t0 + (pr[i] >> 6);
        const int u = pr[i] & 63;
        pSrc[i] = srcB + (size_t)t * JD + pg[i] * 8;
        pTgt[i] = tgtB + (size_t)u * JD + pg[i] * 8;
        pWh[i]  = g_Wh + (size_t)(n0 + pr[i]) * JD + pg[i] * 8;
        pWl[i]  = g_Wl + (size_t)(n0 + pr[i]) * JD + pg[i] * 8;
        stsOff[i] = (uint32_t)(pr[i] * ROWB + pg[i] * 16);
    }

    float acc[4][4][4];
#pragma unroll
    for (int mt = 0; mt < 4; mt++)
#pragma unroll
        for (int nt = 0; nt < 4; nt++)
#pragma unroll
            for (int j = 0; j < 4; j++) acc[mt][nt][j] = 0.0f;

    // lane offsets for ldmatrix
    const uint32_t aLane = (uint32_t)((lid & 15) * ROWB + (lid >> 4) * 16);
    const uint32_t bLane = (uint32_t)((lid & 7) * ROWB + ((lid >> 3) & 1) * 16);

    // ---- prologue: produce chunk 0 into stage 0 ----
    {
#pragma unroll
        for (int i = 0; i < 2; i++) {
            cp16(sb + S_BH(0) + stsOff[i], pWh[i]);
            cp16(sb + S_BL(0) + stsOff[i], pWl[i]);
        }
        CP_COMMIT();
#pragma unroll
        for (int i = 0; i < 2; i++) {
            const float4 s0 = *(const float4*)(pSrc[i]);
            const float4 s1 = *(const float4*)(pSrc[i] + 4);
            const float4 t4 = *(const float4*)(pTgt[i]);
            const float4 t5 = *(const float4*)(pTgt[i] + 4);
            uint4 hv, lv;
            split2(fmaxf(s0.x + t4.x, 0.f), fmaxf(s0.y + t4.y, 0.f), hv.x, lv.x);
            split2(fmaxf(s0.z + t4.z, 0.f), fmaxf(s0.w + t4.w, 0.f), hv.y, lv.y);
            split2(fmaxf(s1.x + t5.x, 0.f), fmaxf(s1.y + t5.y, 0.f), hv.z, lv.z);
            split2(fmaxf(s1.z + t5.z, 0.f), fmaxf(s1.w + t5.w, 0.f), hv.w, lv.w);
            *(uint4*)(smem + S_AH(0) + stsOff[i]) = hv;
            *(uint4*)(smem + S_AL(0) + stsOff[i]) = lv;
        }
        CP_WAIT0();
        __syncthreads();
    }

    for (int c = 0; c < NCH; c++) {
        const int s = c & 1;
        const int s1 = s ^ 1;
        float4 sv[2][2], tv[2][2];

        if (c + 1 < NCH) {
            const int k1 = (c + 1) * BK;
            // B: cp.async into next stage
#pragma unroll
            for (int i = 0; i < 2; i++) {
                cp16(sb + S_BH(s1) + stsOff[i], pWh[i] + k1);
                cp16(sb + S_BL(s1) + stsOff[i], pWl[i] + k1);
            }
            CP_COMMIT();
            // A: LDG into regs (latency hidden under MMA below)
#pragma unroll
            for (int i = 0; i < 2; i++) {
                sv[i][0] = *(const float4*)(pSrc[i] + k1);
                sv[i][1] = *(const float4*)(pSrc[i] + k1 + 4);
                tv[i][0] = *(const float4*)(pTgt[i] + k1);
                tv[i][1] = *(const float4*)(pTgt[i] + k1 + 4);
            }
        }

        // ---- MMA on stage s ----
        const uint32_t aH = sb + S_AH(s) + (uint32_t)(mw * 64 * ROWB) + aLane;
        const uint32_t aL = sb + S_AL(s) + (uint32_t)(mw * 64 * ROWB) + aLane;
        const uint32_t bH = sb + S_BH(s) + (uint32_t)(nw * 32 * ROWB) + bLane;
        const uint32_t bL = sb + S_BL(s) + (uint32_t)(nw * 32 * ROWB) + bLane;

#pragma unroll
        for (int kk = 0; kk < 2; kk++) {
            uint32_t ah[4][4], al[4][4], bh[4][2], bl[4][2];
#pragma unroll
            for (int mt = 0; mt < 4; mt++) ldsm_x4(ah[mt], aH + mt * 16 * ROWB + kk * 32);
#pragma unroll
            for (int nt = 0; nt < 4; nt++) ldsm_x2(bh[nt], bH + nt * 8 * ROWB + kk * 32);
#pragma unroll
            for (int mt = 0; mt < 4; mt++)
#pragma unroll
                for (int nt = 0; nt < 4; nt++) mma16816(acc[mt][nt], ah[mt], bh[nt]);

#pragma unroll
            for (int nt = 0; nt < 4; nt++) ldsm_x2(bl[nt], bL + nt * 8 * ROWB + kk * 32);
#pragma unroll
            for (int mt = 0; mt < 4; mt++)
#pragma unroll
                for (int nt = 0; nt < 4; nt++) mma16816(acc[mt][nt], ah[mt], bl[nt]);

#pragma unroll
            for (int mt = 0; mt < 4; mt++) ldsm_x4(al[mt], aL + mt * 16 * ROWB + kk * 32);
#pragma unroll
            for (int mt = 0; mt < 4; mt++)
#pragma unroll
                for (int nt = 0; nt < 4; nt++) mma16816(acc[mt][nt], al[mt], bh[nt]);
        }

        if (c + 1 < NCH) {
            // split + STS A(c+1)
#pragma unroll
            for (int i = 0; i < 2; i++) {
                uint4 hv, lv;
                split2(fmaxf(sv[i][0].x + tv[i][0].x, 0.f), fmaxf(sv[i][0].y + tv[i][0].y, 0.f), hv.x, lv.x);
                split2(fmaxf(sv[i][0].z + tv[i][0].z, 0.f), fmaxf(sv[i][0].w + tv[i][0].w, 0.f), hv.y, lv.y);
                split2(fmaxf(sv[i][1].x + tv[i][1].x, 0.f), fmaxf(sv[i][1].y + tv[i][1].y, 0.f), hv.z, lv.z);
                split2(fmaxf(sv[i][1].z + tv[i][1].z, 0.f), fmaxf(sv[i][1].w + tv[i][1].w, 0.f), hv.w, lv.w);
                *(uint4*)(smem + S_AH(s1) + stsOff[i]) = hv;
                *(uint4*)(smem + S_AL(s1) + stsOff[i]) = lv;
            }
            CP_WAIT0();
        }
        __syncthreads();
    }

    // ---- epilogue: bias + store ----
    const int wm0 = m0 + mw * 64;
    const int wn0 = n0 + nw * 32;
    float2 bv[4];
#pragma unroll
    for (int nt = 0; nt < 4; nt++)
        bv[nt] = *(const float2*)(bias + wn0 + nt * 8 + (lid & 3) * 2);

#pragma unroll
    for (int mt = 0; mt < 4; mt++) {
        const int r0 = wm0 + mt * 16 + (lid >> 2);
        float* p0 = out + (size_t)r0 * JV + wn0 + (lid & 3) * 2;
        float* p1 = p0 + (size_t)8 * JV;
#pragma unroll
        for (int nt = 0; nt < 4; nt++) {
            float2 o0, o1;
            o0.x = acc[mt][nt][0] + bv[nt].x;
            o0.y = acc[mt][nt][1] + bv[nt].y;
            o1.x = acc[mt][nt][2] + bv[nt].x;
            o1.y = acc[mt][nt][3] + bv[nt].y;
            *(float2*)(p0 + nt * 8) = o0;
            *(float2*)(p1 + nt * 8) = o1;
        }
    }
}

extern "C" void kernel_launch(void* const* d_in, const int* in_sizes, int n_in,
                              void* d_out, int out_size)
{
    const float* src  = (const float*)d_in[0];
    const int*   sl   = (const int*)  d_in[1];
    const float* tgt  = (const float*)d_in[2];
    const int*   tl   = (const int*)  d_in[3];
    const float* W    = (const float*)d_in[4];
    const float* bias = (const float*)d_in[5];
    float* out = (float*)d_out;

    const long long extra = (long long)out_size - MAIN_OUT;

    wsplit_kernel<<<(JV * JD + 255) / 256, 256>>>(W, sl, tl, out,
                                                  extra > 0 ? (int)extra : 0);

    cudaFuncSetAttribute(joiner_mma_kernel,
                         cudaFuncAttributeMaxDynamicSharedMemorySize, SMEM_TOT);
    dim3 grid(JV / BN, JM / BM);   // (8, 1024)
    joiner_mma_kernel<<<grid, 256, SMEM_TOT>>>(src, tgt, bias, out);
}

// round 7
// speedup vs baseline: 2.3292x; 1.0908x over previous
#include <cuda_runtime.h>
#include <cuda_bf16.h>
#include <cstdint>

// ---------------- problem constants ----------------
#define JB 8
#define JT 256
#define JU 64
#define JD 512
#define JV 1024
#define JM (JB * JT * JU)                 // 131072
#define MAIN_OUT ((long long)JM * JV)     // 134217728

// ---------------- tile config ----------------
#define BM 128
#define BN 128
#define BK 64
#define NCH (JD / BK)          // 8 k-chunks
#define NKK 4                  // k16 steps per chunk

// smem: 128B data row + 16B pad = 144B stride  (conflict-free STS + LDSM)
#define ROWB 144
#define MATB (128 * ROWB)      // 18432 bytes per matrix tile
#define STAGEB (4 * MATB)      // AH, AL, BH, BL = 73728
#define S_AH(s) ((s) * STAGEB)
#define S_AL(s) (S_AH(s) + MATB)
#define S_BH(s) (S_AH(s) + 2 * MATB)
#define S_BL(s) (S_AH(s) + 3 * MATB)
#define SMEM_TOT (2 * STAGEB)  // 147456

// W split into bf16 hi/lo (device scratch; no allocation)
__device__ __nv_bfloat16 g_Wh[JV * JD];
__device__ __nv_bfloat16 g_Wl[JV * JD];

// ---------------- helpers ----------------
__device__ __forceinline__ uint32_t smem_u32(const void* p) {
    uint32_t a;
    asm("{ .reg .u64 t; cvta.to.shared.u64 t, %1; cvt.u32.u64 %0, t; }" : "=r"(a) : "l"(p));
    return a;
}
__device__ __forceinline__ void ldsm_x4(uint32_t* r, uint32_t addr) {
    asm volatile("ldmatrix.sync.aligned.m8n8.x4.shared.b16 {%0,%1,%2,%3}, [%4];"
                 : "=r"(r[0]), "=r"(r[1]), "=r"(r[2]), "=r"(r[3]) : "r"(addr));
}
__device__ __forceinline__ void mma16816(float* d, const uint32_t* a, const uint32_t* b) {
    asm volatile(
        "mma.sync.aligned.m16n8k16.row.col.f32.bf16.bf16.f32 "
        "{%0,%1,%2,%3}, {%4,%5,%6,%7}, {%8,%9}, {%0,%1,%2,%3};"
        : "+f"(d[0]), "+f"(d[1]), "+f"(d[2]), "+f"(d[3])
        : "r"(a[0]), "r"(a[1]), "r"(a[2]), "r"(a[3]), "r"(b[0]), "r"(b[1]));
}
__device__ __forceinline__ void cp16(uint32_t dst, const void* src) {
    asm volatile("cp.async.cg.shared.global [%0], [%1], 16;" :: "r"(dst), "l"(src) : "memory");
}
#define CP_COMMIT() asm volatile("cp.async.commit_group;" ::: "memory")
#define CP_WAIT0()  asm volatile("cp.async.wait_group 0;" ::: "memory")

// split fp32 pair -> packed bf16x2 hi and lo
__device__ __forceinline__ void split2(float x, float y, uint32_t& hi, uint32_t& lo) {
    __nv_bfloat16 hx = __float2bfloat16_rn(x);
    __nv_bfloat16 hy = __float2bfloat16_rn(y);
    float rx = x - __bfloat162float(hx);
    float ry = y - __bfloat162float(hy);
    __nv_bfloat162 h2; h2.x = hx; h2.y = hy;
    __nv_bfloat162 l2; l2.x = __float2bfloat16_rn(rx); l2.y = __float2bfloat16_rn(ry);
    hi = *reinterpret_cast<uint32_t*>(&h2);
    lo = *reinterpret_cast<uint32_t*>(&l2);
}

// ---------------- W split pre-kernel (+ tail lengths passthrough) ----------------
__global__ void wsplit_kernel(const float* __restrict__ W,
                              const int* __restrict__ sl,
                              const int* __restrict__ tl,
                              float* __restrict__ out,
                              int extra)
{
    int i = blockIdx.x * blockDim.x + threadIdx.x;
    if (i < JV * JD) {
        float w = W[i];
        __nv_bfloat16 h = __float2bfloat16_rn(w);
        g_Wh[i] = h;
        g_Wl[i] = __float2bfloat16_rn(w - __bfloat162float(h));
    }
    if (blockIdx.x == 0) {
        int t = threadIdx.x;
        if (t < 8 && t < extra)                 out[MAIN_OUT + t] = (float)sl[t];
        else if (t >= 8 && t < 16 && t < extra) out[MAIN_OUT + t] = (float)tl[t - 8];
    }
}

// ---------------- main HMMA GEMM: 512 threads, 16 warps (4M x 4N), warp 32x32 ----------------
__global__ __launch_bounds__(512, 1)
void joiner_mma_kernel(const float* __restrict__ src,   // [B,T,D]
                       const float* __restrict__ tgt,   // [B,U,D]
                       const float* __restrict__ bias,  // [V]
                       float* __restrict__ out)         // [M,V]
{
    extern __shared__ char smem[];
    const uint32_t sb = smem_u32(smem);
    const int tid = threadIdx.x;
    const int wid = tid >> 5;
    const int lid = tid & 31;
    const int mw = wid >> 2;       // 0..3 (M)
    const int nw = wid & 3;        // 0..3 (N)

    const int n0 = blockIdx.x * BN;
    const int m0 = blockIdx.y * BM;
    const int bidx = m0 / (JT * JU);
    const int t0 = (m0 % (JT * JU)) / JU;     // tile spans t0, t0+1
    const float* srcB = src + (size_t)bidx * JT * JD;
    const float* tgtB = tgt + (size_t)bidx * JU * JD;

    // ---- producer geometry: 2 items/thread, item = one row-r, 8-col group g ----
    const float* pSrc[2];
    const float* pTgt[2];
    const __nv_bfloat16* pWh[2];
    const __nv_bfloat16* pWl[2];
    uint32_t stsOff[2];
#pragma unroll
    for (int i = 0; i < 2; i++) {
        const int idx = tid + i * 512;
        const int r = idx >> 3;        // 0..127
        const int g = idx & 7;         // 0..7 (8 cols each -> 64 k-cols)
        const int t = t0 + (r >> 6);
        const int u = r & 63;
        pSrc[i] = srcB + (size_t)t * JD + g * 8;
        pTgt[i] = tgtB + (size_t)u * JD + g * 8;
        pWh[i]  = g_Wh + (size_t)(n0 + r) * JD + g * 8;
        pWl[i]  = g_Wl + (size_t)(n0 + r) * JD + g * 8;
        stsOff[i] = (uint32_t)(r * ROWB + g * 16);
    }

    float acc[2][4][4];
#pragma unroll
    for (int mt = 0; mt < 2; mt++)
#pragma unroll
        for (int nt = 0; nt < 4; nt++)
#pragma unroll
            for (int j = 0; j < 4; j++) acc[mt][nt][j] = 0.0f;

    // ldmatrix lane offsets
    const uint32_t aLane = (uint32_t)((lid & 15) * ROWB + (lid >> 4) * 16);
    const uint32_t bLane = (uint32_t)((lid & 7) * ROWB + ((lid >> 3) & 1) * 16 + (lid >> 4) * (8 * ROWB));

    // ---- prologue: produce chunk 0 into stage 0 ----
    {
#pragma unroll
        for (int i = 0; i < 2; i++) {
            cp16(sb + S_BH(0) + stsOff[i], pWh[i]);
            cp16(sb + S_BL(0) + stsOff[i], pWl[i]);
        }
        CP_COMMIT();
#pragma unroll
        for (int i = 0; i < 2; i++) {
            const float4 s0 = *(const float4*)(pSrc[i]);
            const float4 s1 = *(const float4*)(pSrc[i] + 4);
            const float4 t4 = *(const float4*)(pTgt[i]);
            const float4 t5 = *(const float4*)(pTgt[i] + 4);
            uint4 hv, lv;
            split2(fmaxf(s0.x + t4.x, 0.f), fmaxf(s0.y + t4.y, 0.f), hv.x, lv.x);
            split2(fmaxf(s0.z + t4.z, 0.f), fmaxf(s0.w + t4.w, 0.f), hv.y, lv.y);
            split2(fmaxf(s1.x + t5.x, 0.f), fmaxf(s1.y + t5.y, 0.f), hv.z, lv.z);
            split2(fmaxf(s1.z + t5.z, 0.f), fmaxf(s1.w + t5.w, 0.f), hv.w, lv.w);
            *(uint4*)(smem + S_AH(0) + stsOff[i]) = hv;
            *(uint4*)(smem + S_AL(0) + stsOff[i]) = lv;
        }
        CP_WAIT0();
        __syncthreads();
    }

    for (int c = 0; c < NCH; c++) {
        const int s = c & 1;
        const int s1 = s ^ 1;
        const bool more = (c + 1 < NCH);
        float4 sv[2][2], tv[2][2];

        if (more) {
            const int k1 = (c + 1) * BK;
#pragma unroll
            for (int i = 0; i < 2; i++) {
                cp16(sb + S_BH(s1) + stsOff[i], pWh[i] + k1);
                cp16(sb + S_BL(s1) + stsOff[i], pWl[i] + k1);
            }
            CP_COMMIT();
#pragma unroll
            for (int i = 0; i < 2; i++) {
                sv[i][0] = *(const float4*)(pSrc[i] + k1);
                sv[i][1] = *(const float4*)(pSrc[i] + k1 + 4);
                tv[i][0] = *(const float4*)(pTgt[i] + k1);
                tv[i][1] = *(const float4*)(pTgt[i] + k1 + 4);
            }
        }

        const uint32_t aHb = sb + S_AH(s) + (uint32_t)(mw * 32 * ROWB) + aLane;
        const uint32_t aLb = sb + S_AL(s) + (uint32_t)(mw * 32 * ROWB) + aLane;
        const uint32_t bHb = sb + S_BH(s) + (uint32_t)(nw * 32 * ROWB) + bLane;
        const uint32_t bLb = sb + S_BL(s) + (uint32_t)(nw * 32 * ROWB) + bLane;

#pragma unroll
        for (int kk = 0; kk < NKK; kk++) {
            uint32_t a[2][4], bh[8], bl[8];
            // A-hi
#pragma unroll
            for (int mt = 0; mt < 2; mt++) ldsm_x4(a[mt], aHb + mt * 16 * ROWB + kk * 32);
            // B-hi: one x4 per nt-pair -> bh[nt*2 + half]
#pragma unroll
            for (int p = 0; p < 2; p++) ldsm_x4(&bh[p * 4], bHb + p * 16 * ROWB + kk * 32);
#pragma unroll
            for (int mt = 0; mt < 2; mt++)
#pragma unroll
                for (int nt = 0; nt < 4; nt++) mma16816(acc[mt][nt], a[mt], &bh[nt * 2]);
            // B-lo
#pragma unroll
            for (int p = 0; p < 2; p++) ldsm_x4(&bl[p * 4], bLb + p * 16 * ROWB + kk * 32);
#pragma unroll
            for (int mt = 0; mt < 2; mt++)
#pragma unroll
                for (int nt = 0; nt < 4; nt++) mma16816(acc[mt][nt], a[mt], &bl[nt * 2]);
            // A-lo reuses a[]
#pragma unroll
            for (int mt = 0; mt < 2; mt++) ldsm_x4(a[mt], aLb + mt * 16 * ROWB + kk * 32);
#pragma unroll
            for (int mt = 0; mt < 2; mt++)
#pragma unroll
                for (int nt = 0; nt < 4; nt++) mma16816(acc[mt][nt], a[mt], &bh[nt * 2]);

            // free the A prefetch registers halfway through the chunk
            if (kk == 1 && more) {
#pragma unroll
                for (int i = 0; i < 2; i++) {
                    uint4 hv, lv;
                    split2(fmaxf(sv[i][0].x + tv[i][0].x, 0.f), fmaxf(sv[i][0].y + tv[i][0].y, 0.f), hv.x, lv.x);
                    split2(fmaxf(sv[i][0].z + tv[i][0].z, 0.f), fmaxf(sv[i][0].w + tv[i][0].w, 0.f), hv.y, lv.y);
                    split2(fmaxf(sv[i][1].x + tv[i][1].x, 0.f), fmaxf(sv[i][1].y + tv[i][1].y, 0.f), hv.z, lv.z);
                    split2(fmaxf(sv[i][1].z + tv[i][1].z, 0.f), fmaxf(sv[i][1].w + tv[i][1].w, 0.f), hv.w, lv.w);
                    *(uint4*)(smem + S_AH(s1) + stsOff[i]) = hv;
                    *(uint4*)(smem + S_AL(s1) + stsOff[i]) = lv;
                }
            }
        }

        if (more) CP_WAIT0();
        __syncthreads();
    }

    // ---- epilogue: bias + store ----
    const int wm0 = m0 + mw * 32;
    const int wn0 = n0 + nw * 32;
    float2 bv[4];
#pragma unroll
    for (int nt = 0; nt < 4; nt++)
        bv[nt] = *(const float2*)(bias + wn0 + nt * 8 + (lid & 3) * 2);

#pragma unroll
    for (int mt = 0; mt < 2; mt++) {
        const int r0 = wm0 + mt * 16 + (lid >> 2);
        float* p0 = out + (size_t)r0 * JV + wn0 + (lid & 3) * 2;
        float* p1 = p0 + (size_t)8 * JV;
#pragma unroll
        for (int nt = 0; nt < 4; nt++) {
            float2 o0, o1;
            o0.x = acc[mt][nt][0] + bv[nt].x;
            o0.y = acc[mt][nt][1] + bv[nt].y;
            o1.x = acc[mt][nt][2] + bv[nt].x;
            o1.y = acc[mt][nt][3] + bv[nt].y;
            *(float2*)(p0 + nt * 8) = o0;
            *(float2*)(p1 + nt * 8) = o1;
        }
    }
}

extern "C" void kernel_launch(void* const* d_in, const int* in_sizes, int n_in,
                              void* d_out, int out_size)
{
    const float* src  = (const float*)d_in[0];
    const int*   sl   = (const int*)  d_in[1];
    const float* tgt  = (const float*)d_in[2];
    const int*   tl   = (const int*)  d_in[3];
    const float* W    = (const float*)d_in[4];
    const float* bias = (const float*)d_in[5];
    float* out = (float*)d_out;

    const long long extra = (long long)out_size - MAIN_OUT;

    wsplit_kernel<<<(JV * JD + 255) / 256, 256>>>(W, sl, tl, out,
                                                  extra > 0 ? (int)extra : 0);

    cudaFuncSetAttribute(joiner_mma_kernel,
                         cudaFuncAttributeMaxDynamicSharedMemorySize, SMEM_TOT);
    dim3 grid(JV / BN, JM / BM);   // (8, 1024)
    joiner_mma_kernel<<<grid, 512, SMEM_TOT>>>(src, tgt, bias, out);
}

// round 9
// speedup vs baseline: 2.4567x; 1.0548x over previous
#include <cuda_runtime.h>
#include <cuda_bf16.h>
#include <cstdint>

// ---------------- problem constants ----------------
#define JB 8
#define JT 256
#define JU 64
#define JD 512
#define JV 1024
#define JM (JB * JT * JU)                 // 131072
#define MAIN_OUT ((long long)JM * JV)     // 134217728

// ---------------- tile config ----------------
#define BM 128
#define BN 128
#define BK 64
#define KG 256                 // K per group
#define NCHG (KG / BK)         // 4 chunks per group
#define NKK 4                  // k16 steps per chunk

// smem rows: 128B data + 16B pad = 144B (conflict-free STS + LDSM)
#define ROWB 144
#define MATB (128 * ROWB)          // 18432
// group region: AH, AL, BH0, BL0, BH1, BL1
#define GRPB (6 * MATB)            // 110592
#define SMEM_TOT (2 * GRPB)        // 221184
#define O_AH(g)    ((g) * GRPB)
#define O_AL(g)    (O_AH(g) + MATB)
#define O_BH(g, s) (O_AH(g) + (2 + 2 * (s)) * MATB)
#define O_BL(g, s) (O_BH(g, s) + MATB)
// epilogue partial buffer: reuse group-1 region; row stride 132 floats (528B)
#define O_PART GRPB
#define PSTR 132

// W split into bf16 hi/lo (device scratch; no allocation)
__device__ __nv_bfloat16 g_Wh[JV * JD];
__device__ __nv_bfloat16 g_Wl[JV * JD];

// ---------------- helpers ----------------
__device__ __forceinline__ uint32_t smem_u32(const void* p) {
    uint32_t a;
    asm("{ .reg .u64 t; cvta.to.shared.u64 t, %1; cvt.u32.u64 %0, t; }" : "=r"(a) : "l"(p));
    return a;
}
__device__ __forceinline__ void ldsm_x4(uint32_t* r, uint32_t addr) {
    asm volatile("ldmatrix.sync.aligned.m8n8.x4.shared.b16 {%0,%1,%2,%3}, [%4];"
                 : "=r"(r[0]), "=r"(r[1]), "=r"(r[2]), "=r"(r[3]) : "r"(addr));
}
__device__ __forceinline__ void mma16816(float* d, const uint32_t* a, const uint32_t* b) {
    asm volatile(
        "mma.sync.aligned.m16n8k16.row.col.f32.bf16.bf16.f32 "
        "{%0,%1,%2,%3}, {%4,%5,%6,%7}, {%8,%9}, {%0,%1,%2,%3};"
        : "+f"(d[0]), "+f"(d[1]), "+f"(d[2]), "+f"(d[3])
        : "r"(a[0]), "r"(a[1]), "r"(a[2]), "r"(a[3]), "r"(b[0]), "r"(b[1]));
}
__device__ __forceinline__ void cp16(uint32_t dst, const void* src) {
    asm volatile("cp.async.cg.shared.global [%0], [%1], 16;" :: "r"(dst), "l"(src) : "memory");
}
#define CP_COMMIT() asm volatile("cp.async.commit_group;" ::: "memory")
#define CP_WAIT1()  asm volatile("cp.async.wait_group 1;" ::: "memory")
#define CP_WAIT0()  asm volatile("cp.async.wait_group 0;" ::: "memory")
#define GBAR(id)    asm volatile("bar.sync %0, 256;" :: "r"(id) : "memory")

// split fp32 pair -> packed bf16x2 hi and lo
__device__ __forceinline__ void split2(float x, float y, uint32_t& hi, uint32_t& lo) {
    __nv_bfloat16 hx = __float2bfloat16_rn(x);
    __nv_bfloat16 hy = __float2bfloat16_rn(y);
    float rx = x - __bfloat162float(hx);
    float ry = y - __bfloat162float(hy);
    __nv_bfloat162 h2; h2.x = hx; h2.y = hy;
    __nv_bfloat162 l2; l2.x = __float2bfloat16_rn(rx); l2.y = __float2bfloat16_rn(ry);
    hi = *reinterpret_cast<uint32_t*>(&h2);
    lo = *reinterpret_cast<uint32_t*>(&l2);
}

// ---------------- W split pre-kernel (+ tail lengths passthrough) ----------------
__global__ void wsplit_kernel(const float* __restrict__ W,
                              const int* __restrict__ sl,
                              const int* __restrict__ tl,
                              float* __restrict__ out,
                              int extra)
{
    int i = blockIdx.x * blockDim.x + threadIdx.x;
    if (i < JV * JD) {
        float w = W[i];
        __nv_bfloat16 h = __float2bfloat16_rn(w);
        g_Wh[i] = h;
        g_Wl[i] = __float2bfloat16_rn(w - __bfloat162float(h));
    }
    if (blockIdx.x == 0) {
        int t = threadIdx.x;
        if (t < 8 && t < extra)                 out[MAIN_OUT + t] = (float)sl[t];
        else if (t >= 8 && t < 16 && t < extra) out[MAIN_OUT + t] = (float)tl[t - 8];
    }
}

// ---------------- main HMMA GEMM: 512 thr = 2 groups x 8 warps, split-K in CTA ----------------
__global__ __launch_bounds__(512, 1)
void joiner_mma_kernel(const float* __restrict__ src,   // [B,T,D]
                       const float* __restrict__ tgt,   // [B,U,D]
                       const float* __restrict__ bias,  // [V]
                       float* __restrict__ out)         // [M,V]
{
    extern __shared__ char smem[];
    const uint32_t sb = smem_u32(smem);
    const int tid  = threadIdx.x;
    const int grp  = tid >> 8;          // 0 or 1
    const int gtid = tid & 255;
    const int wid  = gtid >> 5;         // 0..7 within group
    const int lid  = tid & 31;
    const int mw   = wid >> 2;          // 0..1 -> 64-row half
    const int nw   = wid & 3;           // 0..3 -> 32-col quarter

    const int n0 = blockIdx.x * BN;
    const int m0 = blockIdx.y * BM;
    const int bidx = m0 / (JT * JU);
    const int t0 = (m0 % (JT * JU)) / JU;     // tile spans t0, t0+1
    const int kbase = grp * KG;

    // ---- producer geometry: 4 items/thread; item i covers row r=rbase+32i, cols g*8..g*8+7
    const int rbase = gtid >> 3;        // 0..31
    const int gcol  = gtid & 7;         // 0..7
    const float* srcP0 = src + (size_t)bidx * JT * JD + (size_t)t0 * JD + kbase + gcol * 8;
    const float* srcP1 = srcP0 + JD;
    const float* tgtP0 = tgt + (size_t)bidx * JU * JD + (size_t)rbase * JD + kbase + gcol * 8;
    const float* tgtP1 = tgtP0 + (size_t)32 * JD;
    const __nv_bfloat16* whP = g_Wh + (size_t)(n0 + rbase) * JD + kbase + gcol * 8;
    const __nv_bfloat16* wlP = g_Wl + (size_t)(n0 + rbase) * JD + kbase + gcol * 8;
    const uint32_t stsBase = (uint32_t)(rbase * ROWB + gcol * 16);   // + i*32*ROWB per item

    float acc[4][4][4];
#pragma unroll
    for (int mt = 0; mt < 4; mt++)
#pragma unroll
        for (int nt = 0; nt < 4; nt++)
#pragma unroll
            for (int j = 0; j < 4; j++) acc[mt][nt][j] = 0.0f;

    // ldmatrix lane offsets
    const uint32_t aLane = (uint32_t)((lid & 15) * ROWB + (lid >> 4) * 16);
    const uint32_t bLane = (uint32_t)((lid & 7) * ROWB + ((lid >> 3) & 1) * 16 + (lid >> 4) * (8 * ROWB));
    const int barid = 1 + grp;

    // ---- prologue: cp.async B chunk 0 into stage 0 ----
#pragma unroll
    for (int i = 0; i < 4; i++) {
        cp16(sb + O_BH(grp, 0) + stsBase + i * (32 * ROWB), whP + (size_t)i * 32 * JD);
        cp16(sb + O_BL(grp, 0) + stsBase + i * (32 * ROWB), wlP + (size_t)i * 32 * JD);
    }
    CP_COMMIT();

    for (int c = 0; c < NCHG; c++) {
        const int s = c & 1;
        const int k0 = c * BK;

        // ---- produce A chunk c (exposed; overlapped by the other group's compute) ----
#pragma unroll
        for (int i = 0; i < 4; i++) {
            const float* sp = (i < 2 ? srcP0 : srcP1) + k0;
            const float* tp = ((i & 1) ? tgtP1 : tgtP0) + k0;
            const float4 s0 = *(const float4*)(sp);
            const float4 s1 = *(const float4*)(sp + 4);
            const float4 t4 = *(const float4*)(tp);
            const float4 t5 = *(const float4*)(tp + 4);
            uint4 hv, lv;
            split2(fmaxf(s0.x + t4.x, 0.f), fmaxf(s0.y + t4.y, 0.f), hv.x, lv.x);
            split2(fmaxf(s0.z + t4.z, 0.f), fmaxf(s0.w + t4.w, 0.f), hv.y, lv.y);
            split2(fmaxf(s1.x + t5.x, 0.f), fmaxf(s1.y + t5.y, 0.f), hv.z, lv.z);
            split2(fmaxf(s1.z + t5.z, 0.f), fmaxf(s1.w + t5.w, 0.f), hv.w, lv.w);
            const uint32_t so = stsBase + i * (32 * ROWB);
            *(uint4*)(smem + O_AH(grp) + so) = hv;
            *(uint4*)(smem + O_AL(grp) + so) = lv;
        }

        // ---- issue cp.async B chunk c+1 into the other stage ----
        if (c + 1 < NCHG) {
            const int k1 = k0 + BK;
#pragma unroll
            for (int i = 0; i < 4; i++) {
                cp16(sb + O_BH(grp, s ^ 1) + stsBase + i * (32 * ROWB), whP + (size_t)i * 32 * JD + k1);
                cp16(sb + O_BL(grp, s ^ 1) + stsBase + i * (32 * ROWB), wlP + (size_t)i * 32 * JD + k1);
            }
            CP_COMMIT();
            CP_WAIT1();          // chunk c's B is complete; c+1 may stay in flight
        } else {
            CP_WAIT0();
        }
        GBAR(barid);             // group barrier: tiles for chunk c ready

        // ---- compute chunk c: warp tile 64x32 ----
        const uint32_t aHb = sb + O_AH(grp) + (uint32_t)(mw * 64 * ROWB) + aLane;
        const uint32_t aLb = sb + O_AL(grp) + (uint32_t)(mw * 64 * ROWB) + aLane;
        const uint32_t bHb = sb + O_BH(grp, s) + (uint32_t)(nw * 32 * ROWB) + bLane;
        const uint32_t bLb = sb + O_BL(grp, s) + (uint32_t)(nw * 32 * ROWB) + bLane;

#pragma unroll
        for (int kk = 0; kk < NKK; kk++) {
            uint32_t a[4][4], bh[8], bl[8];
#pragma unroll
            for (int mt = 0; mt < 4; mt++) ldsm_x4(a[mt], aHb + mt * 16 * ROWB + kk * 32);
#pragma unroll
            for (int p = 0; p < 2; p++) ldsm_x4(&bh[p * 4], bHb + p * 16 * ROWB + kk * 32);
#pragma unroll
            for (int mt = 0; mt < 4; mt++)
#pragma unroll
                for (int nt = 0; nt < 4; nt++) mma16816(acc[mt][nt], a[mt], &bh[nt * 2]);
#pragma unroll
            for (int p = 0; p < 2; p++) ldsm_x4(&bl[p * 4], bLb + p * 16 * ROWB + kk * 32);
#pragma unroll
            for (int mt = 0; mt < 4; mt++)
#pragma unroll
                for (int nt = 0; nt < 4; nt++) mma16816(acc[mt][nt], a[mt], &bl[nt * 2]);
#pragma unroll
            for (int mt = 0; mt < 4; mt++) ldsm_x4(a[mt], aLb + mt * 16 * ROWB + kk * 32);
#pragma unroll
            for (int mt = 0; mt < 4; mt++)
#pragma unroll
                for (int nt = 0; nt < 4; nt++) mma16816(acc[mt][nt], a[mt], &bh[nt * 2]);
        }
        GBAR(barid);             // safe to overwrite A / reuse B stage
    }

    // ---- epilogue: group 1 spills partials to smem; group 0 reduces + bias + store ----
    if (grp == 1) {
#pragma unroll
        for (int mt = 0; mt < 4; mt++) {
            const int r0 = mw * 64 + mt * 16 + (lid >> 2);
#pragma unroll
            for (int nt = 0; nt < 4; nt++) {
                const int cc = nw * 32 + nt * 8 + (lid & 3) * 2;
                float2 v0, v1;
                v0.x = acc[mt][nt][0]; v0.y = acc[mt][nt][1];
                v1.x = acc[mt][nt][2]; v1.y = acc[mt][nt][3];
                *(float2*)(smem + O_PART + (size_t)r0 * (PSTR * 4) + cc * 4) = v0;
                *(float2*)(smem + O_PART + (size_t)(r0 + 8) * (PSTR * 4) + cc * 4) = v1;
            }
        }
    }
    __syncthreads();
    if (grp == 0) {
        float2 bv[4];
#pragma unroll
        for (int nt = 0; nt < 4; nt++)
            bv[nt] = *(const float2*)(bias + n0 + nw * 32 + nt * 8 + (lid & 3) * 2);
#pragma unroll
        for (int mt = 0; mt < 4; mt++) {
            const int r0 = mw * 64 + mt * 16 + (lid >> 2);
            float* p0 = out + (size_t)(m0 + r0) * JV + n0;
            float* p1 = out + (size_t)(m0 + r0 + 8) * JV + n0;
#pragma unroll
            for (int nt = 0; nt < 4; nt++) {
                const int cc = nw * 32 + nt * 8 + (lid & 3) * 2;
                const float2 q0 = *(const float2*)(smem + O_PART + (size_t)r0 * (PSTR * 4) + cc * 4);
                const float2 q1 = *(const float2*)(smem + O_PART + (size_t)(r0 + 8) * (PSTR * 4) + cc * 4);
                float2 o0, o1;
                o0.x = acc[mt][nt][0] + q0.x + bv[nt].x;
                o0.y = acc[mt][nt][1] + q0.y + bv[nt].y;
                o1.x = acc[mt][nt][2] + q1.x + bv[nt].x;
                o1.y = acc[mt][nt][3] + q1.y + bv[nt].y;
                *(float2*)(p0 + cc) = o0;
                *(float2*)(p1 + cc) = o1;
            }
        }
    }
}

extern "C" void kernel_launch(void* const* d_in, const int* in_sizes, int n_in,
                              void* d_out, int out_size)
{
    const float* src  = (const float*)d_in[0];
    const int*   sl   = (const int*)  d_in[1];
    const float* tgt  = (const float*)d_in[2];
    const int*   tl   = (const int*)  d_in[3];
    const float* W    = (const float*)d_in[4];
    const float* bias = (const float*)d_in[5];
    float* out = (float*)d_out;

    const long long extra = (long long)out_size - MAIN_OUT;

    wsplit_kernel<<<(JV * JD + 255) / 256, 256>>>(W, sl, tl, out,
                                                  extra > 0 ? (int)extra : 0);

    cudaFuncSetAttribute(joiner_mma_kernel,
                         cudaFuncAttributeMaxDynamicSharedMemorySize, SMEM_TOT);
    dim3 grid(JV / BN, JM / BM);   // (8, 1024)
    joiner_mma_kernel<<<grid, 512, SMEM_TOT>>>(src, tgt, bias, out);
}

// round 10
// speedup vs baseline: 3.3671x; 1.3705x over previous
#include <cuda_runtime.h>
#include <cuda_fp16.h>
#include <cstdint>

// ---------------- problem constants ----------------
#define JB 8
#define JT 256
#define JU 64
#define JD 512
#define JV 1024
#define JM (JB * JT * JU)                 // 131072
#define MAIN_OUT ((long long)JM * JV)     // 134217728

// ---------------- tile config ----------------
#define BM 128
#define BN 256
#define BK 64
#define NCH (JD / BK)          // 8 k-chunks
#define NKK 4                  // k16 steps per chunk

// smem rows: 128B data + 16B pad = 144B (conflict-free STS + LDSM)
#define ROWB 144
#define MATB (128 * ROWB)          // 18432 (one 128-row A matrix)
#define BMATB (256 * ROWB)         // 36864 (one 256-row B matrix)
// A: double-buffered (AH, AL per stage); B: triple-buffered fp16
#define S_A(s)  ((s) * 2 * MATB)            // AH at S_A, AL at S_A + MATB
#define O_B(j)  (4 * MATB + (j) * BMATB)
#define SMEM_TOT (4 * MATB + 3 * BMATB)     // 73728 + 110592 = 184320

// W as fp16 (device scratch; no allocation)
__device__ __half g_Wf[JV * JD];

// ---------------- helpers ----------------
__device__ __forceinline__ uint32_t smem_u32(const void* p) {
    uint32_t a;
    asm("{ .reg .u64 t; cvta.to.shared.u64 t, %1; cvt.u32.u64 %0, t; }" : "=r"(a) : "l"(p));
    return a;
}
__device__ __forceinline__ void ldsm_x4(uint32_t* r, uint32_t addr) {
    asm volatile("ldmatrix.sync.aligned.m8n8.x4.shared.b16 {%0,%1,%2,%3}, [%4];"
                 : "=r"(r[0]), "=r"(r[1]), "=r"(r[2]), "=r"(r[3]) : "r"(addr));
}
__device__ __forceinline__ void mma16816(float* d, const uint32_t* a, const uint32_t* b) {
    asm volatile(
        "mma.sync.aligned.m16n8k16.row.col.f32.f16.f16.f32 "
        "{%0,%1,%2,%3}, {%4,%5,%6,%7}, {%8,%9}, {%0,%1,%2,%3};"
        : "+f"(d[0]), "+f"(d[1]), "+f"(d[2]), "+f"(d[3])
        : "r"(a[0]), "r"(a[1]), "r"(a[2]), "r"(a[3]), "r"(b[0]), "r"(b[1]));
}
__device__ __forceinline__ void cp16(uint32_t dst, const void* src) {
    asm volatile("cp.async.cg.shared.global [%0], [%1], 16;" :: "r"(dst), "l"(src) : "memory");
}
#define CP_COMMIT() asm volatile("cp.async.commit_group;" ::: "memory")
#define CP_WAIT1()  asm volatile("cp.async.wait_group 1;" ::: "memory")
#define CP_WAIT0()  asm volatile("cp.async.wait_group 0;" ::: "memory")

// split fp32 pair -> packed fp16x2 hi and lo (a = hi + lo to ~2^-22)
__device__ __forceinline__ void split2h(float x, float y, uint32_t& hi, uint32_t& lo) {
    __half hx = __float2half_rn(x);
    __half hy = __float2half_rn(y);
    float rx = x - __half2float(hx);
    float ry = y - __half2float(hy);
    __half2 h2 = __halves2half2(hx, hy);
    __half2 l2 = __halves2half2(__float2half_rn(rx), __float2half_rn(ry));
    hi = *reinterpret_cast<uint32_t*>(&h2);
    lo = *reinterpret_cast<uint32_t*>(&l2);
}

// ---------------- W convert pre-kernel (+ tail lengths passthrough) ----------------
__global__ void wconv_kernel(const float* __restrict__ W,
                             const int* __restrict__ sl,
                             const int* __restrict__ tl,
                             float* __restrict__ out,
                             int extra)
{
    int i = blockIdx.x * blockDim.x + threadIdx.x;
    if (i < JV * JD) g_Wf[i] = __float2half_rn(W[i]);
    if (blockIdx.x == 0) {
        int t = threadIdx.x;
        if (t < 8 && t < extra)                 out[MAIN_OUT + t] = (float)sl[t];
        else if (t >= 8 && t < 16 && t < extra) out[MAIN_OUT + t] = (float)tl[t - 8];
    }
}

// ---------------- main HMMA GEMM: 512 thr, 16 warps (4M x 4N), warp 32x64, fp16 2-pass ----------------
__global__ __launch_bounds__(512, 1)
void joiner_mma_kernel(const float* __restrict__ src,   // [B,T,D]
                       const float* __restrict__ tgt,   // [B,U,D]
                       const float* __restrict__ bias,  // [V]
                       float* __restrict__ out)         // [M,V]
{
    extern __shared__ char smem[];
    const uint32_t sb = smem_u32(smem);
    const int tid = threadIdx.x;
    const int wid = tid >> 5;
    const int lid = tid & 31;
    const int mw  = wid >> 2;      // 0..3 -> 32-row slice
    const int nw  = wid & 3;       // 0..3 -> 64-col slice

    const int n0 = blockIdx.x * BN;
    const int m0 = blockIdx.y * BM;
    const int bidx = m0 / (JT * JU);
    const int t0 = (m0 % (JT * JU)) / JU;     // tile spans t0, t0+1

    // ---- A producer geometry: thread -> row ar (0..127), 16-col group ag (0..3) ----
    const int ar = tid >> 2;
    const int ag = tid & 3;
    const float* srcP = src + (size_t)bidx * JT * JD + (size_t)(t0 + (ar >> 6)) * JD + ag * 16;
    const float* tgtP = tgt + (size_t)bidx * JU * JD + (size_t)(ar & 63) * JD + ag * 16;
    const uint32_t aSts = (uint32_t)(ar * ROWB + ag * 32);

    // ---- B producer geometry: thread -> row br (0..255), 32-col half bh2 ----
    const int br  = tid >> 1;
    const int bh2 = tid & 1;
    const __half* wP = g_Wf + (size_t)(n0 + br) * JD + bh2 * 32;
    const uint32_t bSts = (uint32_t)(br * ROWB + bh2 * 64);

    float acc[2][8][4];
#pragma unroll
    for (int mt = 0; mt < 2; mt++)
#pragma unroll
        for (int nt = 0; nt < 8; nt++)
#pragma unroll
            for (int j = 0; j < 4; j++) acc[mt][nt][j] = 0.0f;

    // ldmatrix lane offsets
    const uint32_t aLane = (uint32_t)((lid & 15) * ROWB + (lid >> 4) * 16);
    const uint32_t bLane = (uint32_t)((lid & 7) * ROWB + ((lid >> 3) & 1) * 16 + (lid >> 4) * (8 * ROWB));

    // ---- A produce (relu(src+tgt), fp16 split) into stage s for k-chunk base k0 ----
    auto produceA = [&](int k0, int s) {
        const float4* sp = (const float4*)(srcP + k0);
        const float4* tp = (const float4*)(tgtP + k0);
        const float4 s0 = sp[0], s1 = sp[1], s2 = sp[2], s3 = sp[3];
        const float4 t4 = tp[0], t5 = tp[1], t6 = tp[2], t7 = tp[3];
        uint4 h0, h1, l0, l1;
        split2h(fmaxf(s0.x + t4.x, 0.f), fmaxf(s0.y + t4.y, 0.f), h0.x, l0.x);
        split2h(fmaxf(s0.z + t4.z, 0.f), fmaxf(s0.w + t4.w, 0.f), h0.y, l0.y);
        split2h(fmaxf(s1.x + t5.x, 0.f), fmaxf(s1.y + t5.y, 0.f), h0.z, l0.z);
        split2h(fmaxf(s1.z + t5.z, 0.f), fmaxf(s1.w + t5.w, 0.f), h0.w, l0.w);
        split2h(fmaxf(s2.x + t6.x, 0.f), fmaxf(s2.y + t6.y, 0.f), h1.x, l1.x);
        split2h(fmaxf(s2.z + t6.z, 0.f), fmaxf(s2.w + t6.w, 0.f), h1.y, l1.y);
        split2h(fmaxf(s3.x + t7.x, 0.f), fmaxf(s3.y + t7.y, 0.f), h1.z, l1.z);
        split2h(fmaxf(s3.z + t7.z, 0.f), fmaxf(s3.w + t7.w, 0.f), h1.w, l1.w);
        *(uint4*)(smem + S_A(s) + aSts)               = h0;
        *(uint4*)(smem + S_A(s) + aSts + 16)          = h1;
        *(uint4*)(smem + S_A(s) + MATB + aSts)        = l0;
        *(uint4*)(smem + S_A(s) + MATB + aSts + 16)   = l1;
    };

    // ---- prologue: cp.async B0, B1; produce A0 ----
#pragma unroll
    for (int j = 0; j < 4; j++) cp16(sb + O_B(0) + bSts + j * 16, wP + j * 8);
    CP_COMMIT();
#pragma unroll
    for (int j = 0; j < 4; j++) cp16(sb + O_B(1) + bSts + j * 16, wP + BK + j * 8);
    CP_COMMIT();
    produceA(0, 0);
    CP_WAIT1();
    __syncthreads();

    const int prodKK = wid & 3;    // stagger producer stalls across warps

    for (int c = 0; c < NCH; c++) {
        const int sA = c & 1;
        const bool more = (c + 1 < NCH);

        // issue B(c+2) two chunks ahead
        if (c + 2 < NCH) {
            const int k2 = (c + 2) * BK;
            const uint32_t bo = O_B((c + 2) % 3);
#pragma unroll
            for (int j = 0; j < 4; j++) cp16(sb + bo + bSts + j * 16, wP + k2 + j * 8);
            CP_COMMIT();
        }

        const uint32_t aHb = sb + S_A(sA) + (uint32_t)(mw * 32 * ROWB) + aLane;
        const uint32_t aLb = aHb + MATB;
        const uint32_t bB  = sb + O_B(c % 3) + (uint32_t)(nw * 64 * ROWB) + bLane;

#pragma unroll
        for (int kk = 0; kk < NKK; kk++) {
            uint32_t a[2][4], b[16];
#pragma unroll
            for (int mt = 0; mt < 2; mt++) ldsm_x4(a[mt], aHb + mt * 16 * ROWB + kk * 32);
#pragma unroll
            for (int p = 0; p < 4; p++) ldsm_x4(&b[p * 4], bB + p * 16 * ROWB + kk * 32);
#pragma unroll
            for (int mt = 0; mt < 2; mt++)
#pragma unroll
                for (int nt = 0; nt < 8; nt++) mma16816(acc[mt][nt], a[mt], &b[nt * 2]);
            // second pass: A-lo with the same B fragments
#pragma unroll
            for (int mt = 0; mt < 2; mt++) ldsm_x4(a[mt], aLb + mt * 16 * ROWB + kk * 32);
#pragma unroll
            for (int mt = 0; mt < 2; mt++)
#pragma unroll
                for (int nt = 0; nt < 8; nt++) mma16816(acc[mt][nt], a[mt], &b[nt * 2]);

            if (more && kk == prodKK) produceA((c + 1) * BK, sA ^ 1);
        }

        if (more) {
            if (c + 2 < NCH) CP_WAIT1(); else CP_WAIT0();
            __syncthreads();
        }
    }

    // ---- epilogue: bias + store ----
    const int wn0 = n0 + nw * 64;
    float2 bv[8];
#pragma unroll
    for (int nt = 0; nt < 8; nt++)
        bv[nt] = *(const float2*)(bias + wn0 + nt * 8 + (lid & 3) * 2);

#pragma unroll
    for (int mt = 0; mt < 2; mt++) {
        const int r0 = m0 + mw * 32 + mt * 16 + (lid >> 2);
        float* p0 = out + (size_t)r0 * JV + wn0 + (lid & 3) * 2;
        float* p1 = p0 + (size_t)8 * JV;
#pragma unroll
        for (int nt = 0; nt < 8; nt++) {
            float2 o0, o1;
            o0.x = acc[mt][nt][0] + bv[nt].x;
            o0.y = acc[mt][nt][1] + bv[nt].y;
            o1.x = acc[mt][nt][2] + bv[nt].x;
            o1.y = acc[mt][nt][3] + bv[nt].y;
            *(float2*)(p0 + nt * 8) = o0;
            *(float2*)(p1 + nt * 8) = o1;
        }
    }
}

extern "C" void kernel_launch(void* const* d_in, const int* in_sizes, int n_in,
                              void* d_out, int out_size)
{
    const float* src  = (const float*)d_in[0];
    const int*   sl   = (const int*)  d_in[1];
    const float* tgt  = (const float*)d_in[2];
    const int*   tl   = (const int*)  d_in[3];
    const float* W    = (const float*)d_in[4];
    const float* bias = (const float*)d_in[5];
    float* out = (float*)d_out;

    const long long extra = (long long)out_size - MAIN_OUT;

    wconv_kernel<<<(JV * JD + 255) / 256, 256>>>(W, sl, tl, out,
                                                 extra > 0 ? (int)extra : 0);

    cudaFuncSetAttribute(joiner_mma_kernel,
                         cudaFuncAttributeMaxDynamicSharedMemorySize, SMEM_TOT);
    dim3 grid(JV / BN, JM / BM);   // (4, 1024)
    joiner_mma_kernel<<<grid, 512, SMEM_TOT>>>(src, tgt, bias, out);
}